// round 15
// baseline (speedup 1.0000x reference)
#include <cuda_runtime.h>
#include <cuda_bf16.h>
#include <stdint.h>

// Problem constants
#define BATCH  2
#define SEQ    2048
#define DMODEL 1024
#define NH     16
#define DKH    64
#define PROMPT 64
#define LTOT   2112   // PROMPT + SEQ
#define MROWS  4096   // BATCH*SEQ
#define NTILES (LTOT / 64)   // 33

// -------------------------- device scratch --------------------------------
__device__ __nv_bfloat16 g_Qhi[BATCH * NH * SEQ * DKH];
__device__ __nv_bfloat16 g_Qlo[BATCH * NH * SEQ * DKH];
__device__ __nv_bfloat16 g_Khi[BATCH * NH * LTOT * DKH];
__device__ __nv_bfloat16 g_Klo[BATCH * NH * LTOT * DKH];
__device__ __nv_bfloat16 g_Vhi[BATCH * NH * LTOT * DKH];
__device__ __nv_bfloat16 g_Vlo[BATCH * NH * LTOT * DKH];
__device__ __nv_bfloat16 g_Xhi[MROWS * DMODEL];
__device__ __nv_bfloat16 g_Xlo[MROWS * DMODEL];
__device__ __nv_bfloat16 g_Whi[4 * DMODEL * DMODEL];  // W^T split: [z][n][k]
__device__ __nv_bfloat16 g_Wlo[4 * DMODEL * DMODEL];
__device__ __nv_bfloat16 g_Chi[MROWS * DMODEL];       // ctx split
__device__ __nv_bfloat16 g_Clo[MROWS * DMODEL];

// -------------------------- helpers ---------------------------------------
__device__ __forceinline__ uint32_t smem_u32(const void* p) {
    uint32_t a;
    asm("{ .reg .u64 t; cvta.to.shared.u64 t, %1; cvt.u32.u64 %0, t; }"
        : "=r"(a) : "l"(p));
    return a;
}

#define SW128(o) ((o) ^ (((o) >> 3) & 0x70))

__device__ __forceinline__ void cp16(uint32_t dst, const void* src) {
    asm volatile("cp.async.cg.shared.global [%0], [%1], 16;"
                 :: "r"(dst), "l"(src));
}
#define CP_COMMIT() asm volatile("cp.async.commit_group;")
#define CP_WAIT1()  asm volatile("cp.async.wait_group 1;")
#define CP_WAIT0()  asm volatile("cp.async.wait_group 0;")

__device__ __forceinline__ void ldmx4(uint32_t& r0, uint32_t& r1, uint32_t& r2,
                                      uint32_t& r3, uint32_t addr) {
    asm volatile("ldmatrix.sync.aligned.m8n8.x4.shared.b16 {%0,%1,%2,%3}, [%4];"
                 : "=r"(r0), "=r"(r1), "=r"(r2), "=r"(r3) : "r"(addr));
}

__device__ __forceinline__ void ldmx4t(uint32_t& r0, uint32_t& r1, uint32_t& r2,
                                       uint32_t& r3, uint32_t addr) {
    asm volatile(
        "ldmatrix.sync.aligned.m8n8.x4.trans.shared.b16 {%0,%1,%2,%3}, [%4];"
        : "=r"(r0), "=r"(r1), "=r"(r2), "=r"(r3) : "r"(addr));
}

__device__ __forceinline__ void mma_bf16(float* d, const uint32_t* a,
                                         const uint32_t* b) {
    asm volatile(
        "mma.sync.aligned.m16n8k16.row.col.f32.bf16.bf16.f32 "
        "{%0,%1,%2,%3}, {%4,%5,%6,%7}, {%8,%9}, {%0,%1,%2,%3};"
        : "+f"(d[0]), "+f"(d[1]), "+f"(d[2]), "+f"(d[3])
        : "r"(a[0]), "r"(a[1]), "r"(a[2]), "r"(a[3]), "r"(b[0]), "r"(b[1]));
}

// Fast truncation split (see R14): hi via PRMT, lo via exact residual + cvt.
__device__ __forceinline__ void split2(float a, float b, uint32_t& hi,
                                       uint32_t& lo) {
    uint32_t ua = __float_as_uint(a), ub = __float_as_uint(b);
    uint32_t h;
    asm("prmt.b32 %0, %1, %2, 0x7632;" : "=r"(h) : "r"(ua), "r"(ub));
    float la = a - __uint_as_float(ua & 0xFFFF0000u);
    float lb = b - __uint_as_float(ub & 0xFFFF0000u);
    asm("cvt.rn.bf16x2.f32 %0, %1, %2;" : "=r"(lo) : "f"(lb), "f"(la));
    hi = h;
}

__device__ __forceinline__ void split1(float v, __nv_bfloat16& h,
                                       __nv_bfloat16& l) {
    uint32_t uv = __float_as_uint(v);
    uint16_t hb = (uint16_t)(uv >> 16);
    float lf = v - __uint_as_float(uv & 0xFFFF0000u);
    h = __ushort_as_bfloat16(hb);
    l = __float2bfloat16(lf);
}

// -------------------------- prep kernels -----------------------------------
__global__ void prep_x_kernel(const float* __restrict__ X) {
    int i = (blockIdx.x * blockDim.x + threadIdx.x) * 4;
    float4 v = *(const float4*)&X[i];
    uint32_t h0, l0, h1, l1;
    split2(v.x, v.y, h0, l0);
    split2(v.z, v.w, h1, l1);
    *(uint2*)&g_Xhi[i] = make_uint2(h0, h1);
    *(uint2*)&g_Xlo[i] = make_uint2(l0, l1);
}

__global__ void prep_w_kernel(const float* __restrict__ Wq,
                              const float* __restrict__ Wk,
                              const float* __restrict__ Wv,
                              const float* __restrict__ Wo) {
    __shared__ float t[32][33];
    int z = blockIdx.z;
    const float* __restrict__ W = (z == 0) ? Wq : (z == 1) ? Wk : (z == 2) ? Wv : Wo;
    int x = blockIdx.x * 32 + threadIdx.x;
    int y0 = blockIdx.y * 32;
    for (int i = threadIdx.y; i < 32; i += 8)
        t[i][threadIdx.x] = W[(size_t)(y0 + i) * DMODEL + x];
    __syncthreads();
    size_t base = (size_t)z * DMODEL * DMODEL;
    for (int i = threadIdx.y; i < 32; i += 8) {
        float v = t[threadIdx.x][i];
        int n = blockIdx.x * 32 + i;
        int k = y0 + threadIdx.x;
        __nv_bfloat16 h, l;
        split1(v, h, l);
        g_Whi[base + (size_t)n * DMODEL + k] = h;
        g_Wlo[base + (size_t)n * DMODEL + k] = l;
    }
}

__global__ void copy_prompt_kernel(const float* __restrict__ pk,
                                   const float* __restrict__ pv) {
    int i = blockIdx.x * blockDim.x + threadIdx.x;
    if (i < BATCH * NH * PROMPT * DKH) {
        int d  = i & 63;
        int p  = (i >> 6) & 63;
        int bh = i >> 12;
        int dst = (bh * LTOT + p) * DKH + d;
        __nv_bfloat16 h, l;
        split1(pk[i], h, l);
        g_Khi[dst] = h;
        g_Klo[dst] = l;
        split1(pv[i], h, l);
        g_Vhi[dst] = h;
        g_Vlo[dst] = l;
    }
}

// -------------------------- mma.sync bf16 GEMM: 128m x 64n, 3 CTAs/SM ------
// Warp = 32m x 32n (8 warps: 4m x 2n); acc = 32 regs -> 85-reg budget for
// 3 CTAs/SM (50% more resident warps to hide LDSM/mma latency).
// Stage (24KB): A tile 128 rows x 128B (hi[0,64)|lo[64,128)), B tile 64 rows
// at +16384.  3 stages = 72KB.
__global__ __launch_bounds__(256, 3) void mma_gemm_kernel(int mode,
                                                          float* __restrict__ out) {
    extern __shared__ __align__(1024) char dynG[];
    const uint32_t sb = smem_u32(dynG);

    const int tid = threadIdx.x;
    const int wid = tid >> 5;
    const int lid = tid & 31;
    const int z = blockIdx.z;
    const int m0 = blockIdx.y * 128;
    const int n0 = blockIdx.x * 64;
    const int m_warp = (wid >> 1) * 32;
    const int n_warp = (wid & 1) * 32;

    const __nv_bfloat16* __restrict__ Ahi = (mode == 0) ? g_Xhi : g_Chi;
    const __nv_bfloat16* __restrict__ Alo = (mode == 0) ? g_Xlo : g_Clo;
    const int widx = (mode == 0) ? z : 3;
    const __nv_bfloat16* __restrict__ Bhi = g_Whi + (size_t)widx * DMODEL * DMODEL;
    const __nv_bfloat16* __restrict__ Blo = g_Wlo + (size_t)widx * DMODEL * DMODEL;

    float acc[2][4][4];
#pragma unroll
    for (int i = 0; i < 2; i++)
#pragma unroll
        for (int j = 0; j < 4; j++)
#pragma unroll
            for (int c = 0; c < 4; c++) acc[i][j][c] = 0.f;

    uint32_t a_off[2], a_msk[2];
#pragma unroll
    for (int mt = 0; mt < 2; mt++) {
        int row = m_warp + mt * 16 + (lid & 15);
        int kb = ((lid >> 4) & 1) * 16;
        a_off[mt] = row * 128 + kb;
        a_msk[mt] = (row & 7) << 4;
    }
    uint32_t b_off[2], b_msk[2];
#pragma unroll
    for (int p = 0; p < 2; p++) {
        int g = lid >> 3;
        int row = n_warp + p * 16 + (g >> 1) * 8 + (lid & 7);
        int kb = (g & 1) * 16;
        b_off[p] = row * 128 + kb;
        b_msk[p] = (row & 7) << 4;
    }

    // stage fill: A 16KB (4 cp16/thread) + B 8KB (2 cp16/thread)
    auto issue = [&](int stage, int kc) {
        const int k0 = kc * 32;
        uint32_t ab = sb + stage * 24576;
#pragma unroll
        for (int it = 0; it < 4; it++) {
            int idx = tid + (it << 8);      // 0..1023
            int row = idx >> 3, c = idx & 7;
            int ka = (c & 3) * 8;
            uint32_t off = SW128(row * 128 + c * 16);
            const __nv_bfloat16* __restrict__ Ap = (c < 4) ? Ahi : Alo;
            cp16(ab + off, &Ap[(size_t)(m0 + row) * DMODEL + k0 + ka]);
        }
#pragma unroll
        for (int it = 0; it < 2; it++) {
            int idx = tid + (it << 8);      // 0..511
            int row = idx >> 3, c = idx & 7;
            int ka = (c & 3) * 8;
            uint32_t off = SW128(row * 128 + c * 16);
            const __nv_bfloat16* __restrict__ Bp = (c < 4) ? Bhi : Blo;
            cp16(ab + 16384 + off,
                 &Bp[(size_t)(n0 + row) * DMODEL + k0 + ka]);
        }
        CP_COMMIT();
    };

    issue(0, 0);
    for (int kc = 0; kc < 32; kc++) {
        if (kc + 1 < 32) {
            issue((kc + 1) % 3, kc + 1);
            CP_WAIT1();
        } else {
            CP_WAIT0();
        }
        __syncthreads();

        const uint32_t Ab = sb + (kc % 3) * 24576;
        const uint32_t Bb = Ab + 16384;
#pragma unroll
        for (int ks = 0; ks < 2; ks++) {
            const uint32_t koff = ks * 32;
            uint32_t afh[2][4];
#pragma unroll
            for (int mt = 0; mt < 2; mt++)
                ldmx4(afh[mt][0], afh[mt][1], afh[mt][2], afh[mt][3],
                      Ab + ((a_off[mt] + koff) ^ a_msk[mt]));
            uint32_t bfh[4][2];
#pragma unroll
            for (int p = 0; p < 2; p++) {
                uint32_t r0, r1, r2, r3;
                ldmx4(r0, r1, r2, r3, Bb + ((b_off[p] + koff) ^ b_msk[p]));
                bfh[2 * p][0] = r0;
                bfh[2 * p][1] = r1;
                bfh[2 * p + 1][0] = r2;
                bfh[2 * p + 1][1] = r3;
            }
#pragma unroll
            for (int mt = 0; mt < 2; mt++)
#pragma unroll
                for (int nt = 0; nt < 4; nt++)
                    mma_bf16(acc[mt][nt], afh[mt], bfh[nt]);   // hi*hi
            uint32_t afl[2][4];
#pragma unroll
            for (int mt = 0; mt < 2; mt++)
                ldmx4(afl[mt][0], afl[mt][1], afl[mt][2], afl[mt][3],
                      Ab + ((a_off[mt] + koff + 64) ^ a_msk[mt]));
#pragma unroll
            for (int mt = 0; mt < 2; mt++)
#pragma unroll
                for (int nt = 0; nt < 4; nt++)
                    mma_bf16(acc[mt][nt], afl[mt], bfh[nt]);   // lo*hi
            uint32_t bfl[4][2];
#pragma unroll
            for (int p = 0; p < 2; p++) {
                uint32_t r0, r1, r2, r3;
                ldmx4(r0, r1, r2, r3,
                      Bb + ((b_off[p] + koff + 64) ^ b_msk[p]));
                bfl[2 * p][0] = r0;
                bfl[2 * p][1] = r1;
                bfl[2 * p + 1][0] = r2;
                bfl[2 * p + 1][1] = r3;
            }
#pragma unroll
            for (int mt = 0; mt < 2; mt++)
#pragma unroll
                for (int nt = 0; nt < 4; nt++)
                    mma_bf16(acc[mt][nt], afh[mt], bfl[nt]);   // hi*lo
        }
    }

    const int rowA = lid >> 2;
    const int colA = (lid & 3) * 2;
#pragma unroll
    for (int mt = 0; mt < 2; mt++) {
#pragma unroll
        for (int nt = 0; nt < 4; nt++) {
            int nglob = n0 + n_warp + nt * 8 + colA;
#pragma unroll
            for (int half = 0; half < 2; half++) {
                int m = m0 + m_warp + mt * 16 + rowA + half * 8;
                float vx = acc[mt][nt][half * 2];
                float vy = acc[mt][nt][half * 2 + 1];
                if (mode == 1) {
                    *(float2*)&out[(size_t)m * DMODEL + nglob] =
                        make_float2(vx, vy);
                } else {
                    int b = m >> 11;
                    int s = m & (SEQ - 1);
                    int h = nglob >> 6;
                    int d0 = nglob & 63;
                    size_t idx;
                    uint32_t hi, lo;
                    split2(vx, vy, hi, lo);
                    if (z == 0) {
                        idx = ((size_t)(b * NH + h) * SEQ + s) * DKH + d0;
                        *(uint32_t*)&g_Qhi[idx] = hi;
                        *(uint32_t*)&g_Qlo[idx] = lo;
                    } else if (z == 1) {
                        idx = ((size_t)(b * NH + h) * LTOT + PROMPT + s) * DKH + d0;
                        *(uint32_t*)&g_Khi[idx] = hi;
                        *(uint32_t*)&g_Klo[idx] = lo;
                    } else {
                        idx = ((size_t)(b * NH + h) * LTOT + PROMPT + s) * DKH + d0;
                        *(uint32_t*)&g_Vhi[idx] = hi;
                        *(uint32_t*)&g_Vlo[idx] = lo;
                    }
                }
            }
        }
    }
}

// -------------------------- FA2 attention: 128 q-rows, warp-local softmax --
// (unchanged from round 14)
__global__ __launch_bounds__(256, 2) void attn_mma_kernel(
    const float* __restrict__ bias) {
    extern __shared__ __align__(1024) char dynA[];
    const uint32_t sb = smem_u32(dynA);

    const int tid = threadIdx.x;
    const int wid = tid >> 5, lid = tid & 31;
    const int bh = blockIdx.x, b = bh >> 4, h = bh & 15;
    const int q0 = blockIdx.y * 128;

    const __nv_bfloat16* __restrict__ Qhig = g_Qhi + (size_t)(bh * SEQ + q0) * DKH;
    const __nv_bfloat16* __restrict__ Qlog = g_Qlo + (size_t)(bh * SEQ + q0) * DKH;
    const __nv_bfloat16* __restrict__ Khig = g_Khi + (size_t)bh * LTOT * DKH;
    const __nv_bfloat16* __restrict__ Klog = g_Klo + (size_t)bh * LTOT * DKH;
    const __nv_bfloat16* __restrict__ Vhig = g_Vhi + (size_t)bh * LTOT * DKH;
    const __nv_bfloat16* __restrict__ Vlog = g_Vlo + (size_t)bh * LTOT * DKH;
    const float* __restrict__ Bg = bias + ((size_t)h * SEQ + q0) * LTOT;

    auto issue_kv = [&](int stage, int l0) {
        uint32_t kb2 = sb + stage * 16384;
        uint32_t vb2 = sb + 32768 + stage * 16384;
#pragma unroll
        for (int it = 0; it < 2; it++) {
            int idx = tid + (it << 8);
            int row = idx >> 3, c = idx & 7;
            uint32_t off = SW128(row * 128 + c * 16);
            const size_t g = (size_t)(l0 + row) * DKH + c * 8;
            cp16(kb2 + off, &Khig[g]);
            cp16(kb2 + 8192 + off, &Klog[g]);
            cp16(vb2 + off, &Vhig[g]);
            cp16(vb2 + 8192 + off, &Vlog[g]);
        }
        CP_COMMIT();
    };

    issue_kv(0, 0);

#pragma unroll
    for (int it = 0; it < 4; it++) {
        int idx = tid + it * 256;
        int row = idx >> 3, c = idx & 7;
        uint32_t off = SW128(row * 128 + c * 16);
        *(uint4*)(dynA + 81920 + off) = *(const uint4*)&Qhig[row * DKH + c * 8];
        *(uint4*)(dynA + 65536 + off) = *(const uint4*)&Qlog[row * DKH + c * 8];
    }
    __syncthreads();

    const int qrow = wid * 16 + (lid & 15);
    const uint32_t qboff = qrow * 128 + ((lid >> 4) & 1) * 16;
    const uint32_t qmsk = (qrow & 7) << 4;
    uint32_t qf[4][4];
#pragma unroll
    for (int ks = 0; ks < 4; ks++)
        ldmx4(qf[ks][0], qf[ks][1], qf[ks][2], qf[ks][3],
              sb + 81920 + ((qboff + ks * 32) ^ qmsk));
    const uint32_t qlo_b = sb + 65536;

    uint32_t k_off[4], k_msk[4];
#pragma unroll
    for (int p = 0; p < 4; p++) {
        int g = lid >> 3;
        int row = p * 16 + (g >> 1) * 8 + (lid & 7);
        k_off[p] = row * 128 + (g & 1) * 16;
        k_msk[p] = (row & 7) << 4;
    }
    uint32_t v_off[4];
    const uint32_t v_msk = (lid & 7) << 4;
#pragma unroll
    for (int j = 0; j < 4; j++) {
        int g = lid >> 3;
        int krow = (g & 1) * 8 + (lid & 7);
        int ncol = j * 16 + (g >> 1) * 8;
        v_off[j] = krow * 128 + ncol * 2;
    }

    const int r0 = wid * 16 + (lid >> 2);
    const int r1 = r0 + 8;
    const int scol = (lid & 3) * 2;

    float m_i[2] = {-1e30f, -1e30f};
    float l_i[2] = {0.f, 0.f};
    float o[8][4];
#pragma unroll
    for (int nt = 0; nt < 8; nt++)
#pragma unroll
        for (int c = 0; c < 4; c++) o[nt][c] = 0.f;

    for (int kt = 0; kt < NTILES; kt++) {
        const int l0 = kt * 64;

        float s[8][4];
#pragma unroll
        for (int nt = 0; nt < 8; nt++) {
            int col = l0 + scol + nt * 8;
            float2 b0 = *(const float2*)&Bg[(size_t)r0 * LTOT + col];
            float2 b1 = *(const float2*)&Bg[(size_t)r1 * LTOT + col];
            s[nt][0] = b0.x;
            s[nt][1] = b0.y;
            s[nt][2] = b1.x;
            s[nt][3] = b1.y;
        }

        CP_WAIT0();
        __syncthreads();
        if (kt + 1 < NTILES) issue_kv((kt + 1) & 1, l0 + 64);

        const uint32_t kstage = sb + (kt & 1) * 16384;
        const uint32_t vstage = sb + 32768 + (kt & 1) * 16384;

#pragma unroll
        for (int ks = 0; ks < 4; ks++) {
            uint32_t bf[8][2];
#pragma unroll
            for (int p = 0; p < 4; p++) {
                uint32_t t0, t1, t2, t3;
                ldmx4(t0, t1, t2, t3, kstage + ((k_off[p] + ks * 32) ^ k_msk[p]));
                bf[2 * p][0] = t0;
                bf[2 * p][1] = t1;
                bf[2 * p + 1][0] = t2;
                bf[2 * p + 1][1] = t3;
            }
            uint32_t aq[4];
            ldmx4(aq[0], aq[1], aq[2], aq[3],
                  qlo_b + ((qboff + ks * 32) ^ qmsk));
#pragma unroll
            for (int nt = 0; nt < 8; nt++)
                mma_bf16(s[nt], qf[ks], bf[nt]);
#pragma unroll
            for (int nt = 0; nt < 8; nt++)
                mma_bf16(s[nt], aq, bf[nt]);
        }
#pragma unroll
        for (int ks = 0; ks < 4; ks++) {
            uint32_t bf[8][2];
#pragma unroll
            for (int p = 0; p < 4; p++) {
                uint32_t t0, t1, t2, t3;
                ldmx4(t0, t1, t2, t3,
                      kstage + 8192 + ((k_off[p] + ks * 32) ^ k_msk[p]));
                bf[2 * p][0] = t0;
                bf[2 * p][1] = t1;
                bf[2 * p + 1][0] = t2;
                bf[2 * p + 1][1] = t3;
            }
#pragma unroll
            for (int nt = 0; nt < 8; nt++)
                mma_bf16(s[nt], qf[ks], bf[nt]);
        }

        float mx0 = -1e30f, mx1 = -1e30f;
#pragma unroll
        for (int nt = 0; nt < 8; nt++) {
            mx0 = fmaxf(mx0, fmaxf(s[nt][0], s[nt][1]));
            mx1 = fmaxf(mx1, fmaxf(s[nt][2], s[nt][3]));
        }
        mx0 = fmaxf(mx0, __shfl_xor_sync(0xffffffffu, mx0, 1));
        mx0 = fmaxf(mx0, __shfl_xor_sync(0xffffffffu, mx0, 2));
        mx1 = fmaxf(mx1, __shfl_xor_sync(0xffffffffu, mx1, 1));
        mx1 = fmaxf(mx1, __shfl_xor_sync(0xffffffffu, mx1, 2));
        const float mn0 = fmaxf(m_i[0], mx0);
        const float mn1 = fmaxf(m_i[1], mx1);
        const float sc0 = __expf(m_i[0] - mn0);
        const float sc1 = __expf(m_i[1] - mn1);
        m_i[0] = mn0;
        m_i[1] = mn1;
#pragma unroll
        for (int nt = 0; nt < 8; nt++) {
            o[nt][0] *= sc0;
            o[nt][1] *= sc0;
            o[nt][2] *= sc1;
            o[nt][3] *= sc1;
        }

        float rs0 = 0.f, rs1 = 0.f;
#pragma unroll
        for (int ks = 0; ks < 4; ks++) {
            uint32_t phi_[4], plo_[4];
#pragma unroll
            for (int t = 0; t < 2; t++) {
                int nt = ks * 2 + t;
                float p00 = __expf(s[nt][0] - mn0);
                float p01 = __expf(s[nt][1] - mn0);
                float p10 = __expf(s[nt][2] - mn1);
                float p11 = __expf(s[nt][3] - mn1);
                rs0 += p00 + p01;
                rs1 += p10 + p11;
                split2(p00, p01, phi_[t * 2], plo_[t * 2]);
                split2(p10, p11, phi_[t * 2 + 1], plo_[t * 2 + 1]);
            }
            uint32_t bf[8][2];
#pragma unroll
            for (int j = 0; j < 4; j++) {
                uint32_t t0, t1, t2, t3;
                ldmx4t(t0, t1, t2, t3,
                       vstage + ((v_off[j] + ks * 2048) ^ v_msk));
                bf[2 * j][0] = t0;
                bf[2 * j][1] = t1;
                bf[2 * j + 1][0] = t2;
                bf[2 * j + 1][1] = t3;
            }
#pragma unroll
            for (int nt = 0; nt < 8; nt++)
                mma_bf16(o[nt], phi_, bf[nt]);
#pragma unroll
            for (int nt = 0; nt < 8; nt++)
                mma_bf16(o[nt], plo_, bf[nt]);
#pragma unroll
            for (int j = 0; j < 4; j++) {
                uint32_t t0, t1, t2, t3;
                ldmx4t(t0, t1, t2, t3,
                       vstage + 8192 + ((v_off[j] + ks * 2048) ^ v_msk));
                bf[2 * j][0] = t0;
                bf[2 * j][1] = t1;
                bf[2 * j + 1][0] = t2;
                bf[2 * j + 1][1] = t3;
            }
#pragma unroll
            for (int nt = 0; nt < 8; nt++)
                mma_bf16(o[nt], phi_, bf[nt]);
        }
        rs0 += __shfl_xor_sync(0xffffffffu, rs0, 1);
        rs0 += __shfl_xor_sync(0xffffffffu, rs0, 2);
        rs1 += __shfl_xor_sync(0xffffffffu, rs1, 1);
        rs1 += __shfl_xor_sync(0xffffffffu, rs1, 2);
        l_i[0] = l_i[0] * sc0 + rs0;
        l_i[1] = l_i[1] * sc1 + rs1;
    }

    const float inv0 = 1.0f / l_i[0];
    const float inv1 = 1.0f / l_i[1];
#pragma unroll
    for (int nt = 0; nt < 8; nt++) {
        int col = h * DKH + scol + nt * 8;
        size_t i0 = (size_t)(b * SEQ + q0 + r0) * DMODEL + col;
        size_t i1 = (size_t)(b * SEQ + q0 + r1) * DMODEL + col;
        uint32_t hi, lo;
        split2(o[nt][0] * inv0, o[nt][1] * inv0, hi, lo);
        *(uint32_t*)&g_Chi[i0] = hi;
        *(uint32_t*)&g_Clo[i0] = lo;
        split2(o[nt][2] * inv1, o[nt][3] * inv1, hi, lo);
        *(uint32_t*)&g_Chi[i1] = hi;
        *(uint32_t*)&g_Clo[i1] = lo;
    }
}

// -------------------------- launch ----------------------------------------
extern "C" void kernel_launch(void* const* d_in, const int* in_sizes, int n_in,
                              void* d_out, int out_size) {
    const float* hidden = (const float*)d_in[0];
    const float* pk     = (const float*)d_in[1];
    const float* pv     = (const float*)d_in[2];
    const float* bias   = (const float*)d_in[3];
    const float* Wq     = (const float*)d_in[4];
    const float* Wk     = (const float*)d_in[5];
    const float* Wv     = (const float*)d_in[6];
    const float* Wo     = (const float*)d_in[7];
    float* out = (float*)d_out;

    static int attr_done = 0;
    if (!attr_done) {
        cudaFuncSetAttribute(mma_gemm_kernel,
                             cudaFuncAttributeMaxDynamicSharedMemorySize, 73728);
        cudaFuncSetAttribute(attn_mma_kernel,
                             cudaFuncAttributeMaxDynamicSharedMemorySize, 98304);
        attr_done = 1;
    }

    prep_x_kernel<<<MROWS * DMODEL / 4 / 256, 256>>>(hidden);
    prep_w_kernel<<<dim3(32, 32, 4), dim3(32, 8)>>>(Wq, Wk, Wv, Wo);
    copy_prompt_kernel<<<(BATCH * NH * PROMPT * DKH + 255) / 256, 256>>>(pk, pv);
    mma_gemm_kernel<<<dim3(DMODEL / 64, MROWS / 128, 3), 256, 73728>>>(0, nullptr);
    attn_mma_kernel<<<dim3(BATCH * NH, SEQ / 128), 256, 98304>>>(bias);
    mma_gemm_kernel<<<dim3(DMODEL / 64, MROWS / 128, 1), 256, 73728>>>(1, out);
}

// round 16
// speedup vs baseline: 1.0207x; 1.0207x over previous
#include <cuda_runtime.h>
#include <cuda_bf16.h>
#include <stdint.h>

// Problem constants
#define BATCH  2
#define SEQ    2048
#define DMODEL 1024
#define NH     16
#define DKH    64
#define PROMPT 64
#define LTOT   2112   // PROMPT + SEQ
#define MROWS  4096   // BATCH*SEQ
#define NTILES (LTOT / 64)   // 33

// -------------------------- device scratch --------------------------------
__device__ __nv_bfloat16 g_Qhi[BATCH * NH * SEQ * DKH];
__device__ __nv_bfloat16 g_Qlo[BATCH * NH * SEQ * DKH];
__device__ __nv_bfloat16 g_Khi[BATCH * NH * LTOT * DKH];
__device__ __nv_bfloat16 g_Klo[BATCH * NH * LTOT * DKH];
__device__ __nv_bfloat16 g_Vhi[BATCH * NH * LTOT * DKH];
__device__ __nv_bfloat16 g_Vlo[BATCH * NH * LTOT * DKH];
__device__ __nv_bfloat16 g_Xhi[MROWS * DMODEL];
__device__ __nv_bfloat16 g_Xlo[MROWS * DMODEL];
__device__ __nv_bfloat16 g_Whi[4 * DMODEL * DMODEL];  // W^T split: [z][n][k]
__device__ __nv_bfloat16 g_Wlo[4 * DMODEL * DMODEL];
__device__ __nv_bfloat16 g_Chi[MROWS * DMODEL];       // ctx split
__device__ __nv_bfloat16 g_Clo[MROWS * DMODEL];

// -------------------------- helpers ---------------------------------------
__device__ __forceinline__ uint32_t smem_u32(const void* p) {
    uint32_t a;
    asm("{ .reg .u64 t; cvta.to.shared.u64 t, %1; cvt.u32.u64 %0, t; }"
        : "=r"(a) : "l"(p));
    return a;
}

#define SW128(o) ((o) ^ (((o) >> 3) & 0x70))

__device__ __forceinline__ void cp16(uint32_t dst, const void* src) {
    asm volatile("cp.async.cg.shared.global [%0], [%1], 16;"
                 :: "r"(dst), "l"(src));
}
#define CP_COMMIT() asm volatile("cp.async.commit_group;")
#define CP_WAIT1()  asm volatile("cp.async.wait_group 1;")
#define CP_WAIT0()  asm volatile("cp.async.wait_group 0;")

__device__ __forceinline__ void ldmx4(uint32_t& r0, uint32_t& r1, uint32_t& r2,
                                      uint32_t& r3, uint32_t addr) {
    asm volatile("ldmatrix.sync.aligned.m8n8.x4.shared.b16 {%0,%1,%2,%3}, [%4];"
                 : "=r"(r0), "=r"(r1), "=r"(r2), "=r"(r3) : "r"(addr));
}

__device__ __forceinline__ void ldmx4t(uint32_t& r0, uint32_t& r1, uint32_t& r2,
                                       uint32_t& r3, uint32_t addr) {
    asm volatile(
        "ldmatrix.sync.aligned.m8n8.x4.trans.shared.b16 {%0,%1,%2,%3}, [%4];"
        : "=r"(r0), "=r"(r1), "=r"(r2), "=r"(r3) : "r"(addr));
}

__device__ __forceinline__ void mma_bf16(float* d, const uint32_t* a,
                                         const uint32_t* b) {
    asm volatile(
        "mma.sync.aligned.m16n8k16.row.col.f32.bf16.bf16.f32 "
        "{%0,%1,%2,%3}, {%4,%5,%6,%7}, {%8,%9}, {%0,%1,%2,%3};"
        : "+f"(d[0]), "+f"(d[1]), "+f"(d[2]), "+f"(d[3])
        : "r"(a[0]), "r"(a[1]), "r"(a[2]), "r"(a[3]), "r"(b[0]), "r"(b[1]));
}

// Fast truncation split: hi via PRMT, lo via exact residual + cvt.
__device__ __forceinline__ void split2(float a, float b, uint32_t& hi,
                                       uint32_t& lo) {
    uint32_t ua = __float_as_uint(a), ub = __float_as_uint(b);
    uint32_t h;
    asm("prmt.b32 %0, %1, %2, 0x7632;" : "=r"(h) : "r"(ua), "r"(ub));
    float la = a - __uint_as_float(ua & 0xFFFF0000u);
    float lb = b - __uint_as_float(ub & 0xFFFF0000u);
    asm("cvt.rn.bf16x2.f32 %0, %1, %2;" : "=r"(lo) : "f"(lb), "f"(la));
    hi = h;
}

__device__ __forceinline__ void split1(float v, __nv_bfloat16& h,
                                       __nv_bfloat16& l) {
    uint32_t uv = __float_as_uint(v);
    uint16_t hb = (uint16_t)(uv >> 16);
    float lf = v - __uint_as_float(uv & 0xFFFF0000u);
    h = __ushort_as_bfloat16(hb);
    l = __float2bfloat16(lf);
}

// -------------------------- fused prep kernel -------------------------------
// blockIdx.x < 4096: W transpose+split (z = bx>>10, 32x32 tile index in low bits)
// 4096 <= bx < 6144: X split (grid-stride over 4M elements, f4)
// bx >= 6144: prompt KV split (128K elements)
__global__ __launch_bounds__(256) void prep_all_kernel(
    const float* __restrict__ X,
    const float* __restrict__ pk, const float* __restrict__ pv,
    const float* __restrict__ Wq, const float* __restrict__ Wk,
    const float* __restrict__ Wv, const float* __restrict__ Wo) {
    const int bx = blockIdx.x;
    if (bx < 4096) {
        // W transpose: 32x32 tile, 256 threads (32x8)
        __shared__ float t[32][33];
        int z = bx >> 10;
        int tile = bx & 1023;
        int tx0 = (tile & 31) * 32;   // n base
        int ty0 = (tile >> 5) * 32;   // k base
        const float* __restrict__ W =
            (z == 0) ? Wq : (z == 1) ? Wk : (z == 2) ? Wv : Wo;
        int lx = threadIdx.x & 31;
        int ly = threadIdx.x >> 5;
        for (int i = ly; i < 32; i += 8)
            t[i][lx] = W[(size_t)(ty0 + i) * DMODEL + tx0 + lx];
        __syncthreads();
        size_t base = (size_t)z * DMODEL * DMODEL;
        for (int i = ly; i < 32; i += 8) {
            float v = t[lx][i];
            int n = tx0 + i;
            int k = ty0 + lx;
            __nv_bfloat16 h, l;
            split1(v, h, l);
            g_Whi[base + (size_t)n * DMODEL + k] = h;
            g_Wlo[base + (size_t)n * DMODEL + k] = l;
        }
    } else if (bx < 6144) {
        // X split: 2048 blocks x 256 thr x 2 f4 = 4M elements
        int i = ((bx - 4096) * 512 + threadIdx.x * 2) * 4;
#pragma unroll
        for (int r = 0; r < 2; r++, i += 4) {
            float4 v = *(const float4*)&X[i];
            uint32_t h0, l0, h1, l1;
            split2(v.x, v.y, h0, l0);
            split2(v.z, v.w, h1, l1);
            *(uint2*)&g_Xhi[i] = make_uint2(h0, h1);
            *(uint2*)&g_Xlo[i] = make_uint2(l0, l1);
        }
    } else {
        // prompt KV: 512 blocks x 256 thr = 131072
        int i = (bx - 6144) * 256 + threadIdx.x;
        int d  = i & 63;
        int p  = (i >> 6) & 63;
        int bh = i >> 12;
        int dst = (bh * LTOT + p) * DKH + d;
        __nv_bfloat16 h, l;
        split1(pk[i], h, l);
        g_Khi[dst] = h;
        g_Klo[dst] = l;
        split1(pv[i], h, l);
        g_Vhi[dst] = h;
        g_Vlo[dst] = l;
    }
}

// -------------------------- mma.sync bf16 GEMM (R14 config) -----------------
// 128m x 128n, 2 CTAs/SM. Chunk = 32 k; stage 32KB (A hi|lo interleaved rows,
// B at +16384); 3 stages.
__global__ __launch_bounds__(256, 2) void mma_gemm_kernel(int mode,
                                                          float* __restrict__ out) {
    extern __shared__ __align__(1024) char dynG[];
    const uint32_t sb = smem_u32(dynG);

    const int tid = threadIdx.x;
    const int wid = tid >> 5;
    const int lid = tid & 31;
    const int z = blockIdx.z;
    const int m0 = blockIdx.y * 128;
    const int n0 = blockIdx.x * 128;
    const int m_warp = (wid >> 1) * 32;
    const int n_warp = (wid & 1) * 64;

    const __nv_bfloat16* __restrict__ Ahi = (mode == 0) ? g_Xhi : g_Chi;
    const __nv_bfloat16* __restrict__ Alo = (mode == 0) ? g_Xlo : g_Clo;
    const int widx = (mode == 0) ? z : 3;
    const __nv_bfloat16* __restrict__ Bhi = g_Whi + (size_t)widx * DMODEL * DMODEL;
    const __nv_bfloat16* __restrict__ Blo = g_Wlo + (size_t)widx * DMODEL * DMODEL;

    float acc[2][8][4];
#pragma unroll
    for (int i = 0; i < 2; i++)
#pragma unroll
        for (int j = 0; j < 8; j++)
#pragma unroll
            for (int c = 0; c < 4; c++) acc[i][j][c] = 0.f;

    uint32_t a_off[2], a_msk[2];
#pragma unroll
    for (int mt = 0; mt < 2; mt++) {
        int row = m_warp + mt * 16 + (lid & 15);
        int kb = ((lid >> 4) & 1) * 16;
        a_off[mt] = row * 128 + kb;
        a_msk[mt] = (row & 7) << 4;
    }
    uint32_t b_off[4], b_msk[4];
#pragma unroll
    for (int p = 0; p < 4; p++) {
        int g = lid >> 3;
        int row = n_warp + p * 16 + (g >> 1) * 8 + (lid & 7);
        int kb = (g & 1) * 16;
        b_off[p] = row * 128 + kb;
        b_msk[p] = (row & 7) << 4;
    }

    auto issue = [&](int stage, int kc) {
        const int k0 = kc * 32;
        uint32_t ab = sb + stage * 32768;
#pragma unroll
        for (int it = 0; it < 4; it++) {
            int idx = tid + (it << 8);
            int row = idx >> 3, c = idx & 7;
            int ka = (c & 3) * 8;
            uint32_t off = SW128(row * 128 + c * 16);
            const __nv_bfloat16* __restrict__ Ap = (c < 4) ? Ahi : Alo;
            const __nv_bfloat16* __restrict__ Bp = (c < 4) ? Bhi : Blo;
            cp16(ab + off, &Ap[(size_t)(m0 + row) * DMODEL + k0 + ka]);
            cp16(ab + 16384 + off,
                 &Bp[(size_t)(n0 + row) * DMODEL + k0 + ka]);
        }
        CP_COMMIT();
    };

    issue(0, 0);
    for (int kc = 0; kc < 32; kc++) {
        if (kc + 1 < 32) {
            issue((kc + 1) % 3, kc + 1);
            CP_WAIT1();
        } else {
            CP_WAIT0();
        }
        __syncthreads();

        const uint32_t Ab = sb + (kc % 3) * 32768;
        const uint32_t Bb = Ab + 16384;
#pragma unroll
        for (int ks = 0; ks < 2; ks++) {
            const uint32_t koff = ks * 32;
            uint32_t afh[2][4], afl[2][4];
#pragma unroll
            for (int mt = 0; mt < 2; mt++)
                ldmx4(afh[mt][0], afh[mt][1], afh[mt][2], afh[mt][3],
                      Ab + ((a_off[mt] + koff) ^ a_msk[mt]));
            uint32_t bfh[8][2];
#pragma unroll
            for (int p = 0; p < 4; p++) {
                uint32_t r0, r1, r2, r3;
                ldmx4(r0, r1, r2, r3, Bb + ((b_off[p] + koff) ^ b_msk[p]));
                bfh[2 * p][0] = r0;
                bfh[2 * p][1] = r1;
                bfh[2 * p + 1][0] = r2;
                bfh[2 * p + 1][1] = r3;
            }
#pragma unroll
            for (int mt = 0; mt < 2; mt++)
                ldmx4(afl[mt][0], afl[mt][1], afl[mt][2], afl[mt][3],
                      Ab + ((a_off[mt] + koff + 64) ^ a_msk[mt]));
#pragma unroll
            for (int mt = 0; mt < 2; mt++)
#pragma unroll
                for (int nt = 0; nt < 8; nt++)
                    mma_bf16(acc[mt][nt], afh[mt], bfh[nt]);   // hi*hi
            uint32_t bfl[8][2];
#pragma unroll
            for (int p = 0; p < 4; p++) {
                uint32_t r0, r1, r2, r3;
                ldmx4(r0, r1, r2, r3,
                      Bb + ((b_off[p] + koff + 64) ^ b_msk[p]));
                bfl[2 * p][0] = r0;
                bfl[2 * p][1] = r1;
                bfl[2 * p + 1][0] = r2;
                bfl[2 * p + 1][1] = r3;
            }
#pragma unroll
            for (int mt = 0; mt < 2; mt++)
#pragma unroll
                for (int nt = 0; nt < 8; nt++)
                    mma_bf16(acc[mt][nt], afl[mt], bfh[nt]);   // lo*hi
#pragma unroll
            for (int mt = 0; mt < 2; mt++)
#pragma unroll
                for (int nt = 0; nt < 8; nt++)
                    mma_bf16(acc[mt][nt], afh[mt], bfl[nt]);   // hi*lo
        }
    }

    const int rowA = lid >> 2;
    const int colA = (lid & 3) * 2;
#pragma unroll
    for (int mt = 0; mt < 2; mt++) {
#pragma unroll
        for (int nt = 0; nt < 8; nt++) {
            int nglob = n0 + n_warp + nt * 8 + colA;
#pragma unroll
            for (int half = 0; half < 2; half++) {
                int m = m0 + m_warp + mt * 16 + rowA + half * 8;
                float vx = acc[mt][nt][half * 2];
                float vy = acc[mt][nt][half * 2 + 1];
                if (mode == 1) {
                    *(float2*)&out[(size_t)m * DMODEL + nglob] =
                        make_float2(vx, vy);
                } else {
                    int b = m >> 11;
                    int s = m & (SEQ - 1);
                    int h = nglob >> 6;
                    int d0 = nglob & 63;
                    size_t idx;
                    uint32_t hi, lo;
                    split2(vx, vy, hi, lo);
                    if (z == 0) {
                        idx = ((size_t)(b * NH + h) * SEQ + s) * DKH + d0;
                        *(uint32_t*)&g_Qhi[idx] = hi;
                        *(uint32_t*)&g_Qlo[idx] = lo;
                    } else if (z == 1) {
                        idx = ((size_t)(b * NH + h) * LTOT + PROMPT + s) * DKH + d0;
                        *(uint32_t*)&g_Khi[idx] = hi;
                        *(uint32_t*)&g_Klo[idx] = lo;
                    } else {
                        idx = ((size_t)(b * NH + h) * LTOT + PROMPT + s) * DKH + d0;
                        *(uint32_t*)&g_Vhi[idx] = hi;
                        *(uint32_t*)&g_Vlo[idx] = lo;
                    }
                }
            }
        }
    }
}

// -------------------------- FA2 attention (unchanged R14) -------------------
__global__ __launch_bounds__(256, 2) void attn_mma_kernel(
    const float* __restrict__ bias) {
    extern __shared__ __align__(1024) char dynA[];
    const uint32_t sb = smem_u32(dynA);

    const int tid = threadIdx.x;
    const int wid = tid >> 5, lid = tid & 31;
    const int bh = blockIdx.x, b = bh >> 4, h = bh & 15;
    const int q0 = blockIdx.y * 128;

    const __nv_bfloat16* __restrict__ Qhig = g_Qhi + (size_t)(bh * SEQ + q0) * DKH;
    const __nv_bfloat16* __restrict__ Qlog = g_Qlo + (size_t)(bh * SEQ + q0) * DKH;
    const __nv_bfloat16* __restrict__ Khig = g_Khi + (size_t)bh * LTOT * DKH;
    const __nv_bfloat16* __restrict__ Klog = g_Klo + (size_t)bh * LTOT * DKH;
    const __nv_bfloat16* __restrict__ Vhig = g_Vhi + (size_t)bh * LTOT * DKH;
    const __nv_bfloat16* __restrict__ Vlog = g_Vlo + (size_t)bh * LTOT * DKH;
    const float* __restrict__ Bg = bias + ((size_t)h * SEQ + q0) * LTOT;

    auto issue_kv = [&](int stage, int l0) {
        uint32_t kb2 = sb + stage * 16384;
        uint32_t vb2 = sb + 32768 + stage * 16384;
#pragma unroll
        for (int it = 0; it < 2; it++) {
            int idx = tid + (it << 8);
            int row = idx >> 3, c = idx & 7;
            uint32_t off = SW128(row * 128 + c * 16);
            const size_t g = (size_t)(l0 + row) * DKH + c * 8;
            cp16(kb2 + off, &Khig[g]);
            cp16(kb2 + 8192 + off, &Klog[g]);
            cp16(vb2 + off, &Vhig[g]);
            cp16(vb2 + 8192 + off, &Vlog[g]);
        }
        CP_COMMIT();
    };

    issue_kv(0, 0);

#pragma unroll
    for (int it = 0; it < 4; it++) {
        int idx = tid + it * 256;
        int row = idx >> 3, c = idx & 7;
        uint32_t off = SW128(row * 128 + c * 16);
        *(uint4*)(dynA + 81920 + off) = *(const uint4*)&Qhig[row * DKH + c * 8];
        *(uint4*)(dynA + 65536 + off) = *(const uint4*)&Qlog[row * DKH + c * 8];
    }
    __syncthreads();

    const int qrow = wid * 16 + (lid & 15);
    const uint32_t qboff = qrow * 128 + ((lid >> 4) & 1) * 16;
    const uint32_t qmsk = (qrow & 7) << 4;
    uint32_t qf[4][4];
#pragma unroll
    for (int ks = 0; ks < 4; ks++)
        ldmx4(qf[ks][0], qf[ks][1], qf[ks][2], qf[ks][3],
              sb + 81920 + ((qboff + ks * 32) ^ qmsk));
    const uint32_t qlo_b = sb + 65536;

    uint32_t k_off[4], k_msk[4];
#pragma unroll
    for (int p = 0; p < 4; p++) {
        int g = lid >> 3;
        int row = p * 16 + (g >> 1) * 8 + (lid & 7);
        k_off[p] = row * 128 + (g & 1) * 16;
        k_msk[p] = (row & 7) << 4;
    }
    uint32_t v_off[4];
    const uint32_t v_msk = (lid & 7) << 4;
#pragma unroll
    for (int j = 0; j < 4; j++) {
        int g = lid >> 3;
        int krow = (g & 1) * 8 + (lid & 7);
        int ncol = j * 16 + (g >> 1) * 8;
        v_off[j] = krow * 128 + ncol * 2;
    }

    const int r0 = wid * 16 + (lid >> 2);
    const int r1 = r0 + 8;
    const int scol = (lid & 3) * 2;

    float m_i[2] = {-1e30f, -1e30f};
    float l_i[2] = {0.f, 0.f};
    float o[8][4];
#pragma unroll
    for (int nt = 0; nt < 8; nt++)
#pragma unroll
        for (int c = 0; c < 4; c++) o[nt][c] = 0.f;

    for (int kt = 0; kt < NTILES; kt++) {
        const int l0 = kt * 64;

        float s[8][4];
#pragma unroll
        for (int nt = 0; nt < 8; nt++) {
            int col = l0 + scol + nt * 8;
            float2 b0 = *(const float2*)&Bg[(size_t)r0 * LTOT + col];
            float2 b1 = *(const float2*)&Bg[(size_t)r1 * LTOT + col];
            s[nt][0] = b0.x;
            s[nt][1] = b0.y;
            s[nt][2] = b1.x;
            s[nt][3] = b1.y;
        }

        CP_WAIT0();
        __syncthreads();
        if (kt + 1 < NTILES) issue_kv((kt + 1) & 1, l0 + 64);

        const uint32_t kstage = sb + (kt & 1) * 16384;
        const uint32_t vstage = sb + 32768 + (kt & 1) * 16384;

#pragma unroll
        for (int ks = 0; ks < 4; ks++) {
            uint32_t bf[8][2];
#pragma unroll
            for (int p = 0; p < 4; p++) {
                uint32_t t0, t1, t2, t3;
                ldmx4(t0, t1, t2, t3, kstage + ((k_off[p] + ks * 32) ^ k_msk[p]));
                bf[2 * p][0] = t0;
                bf[2 * p][1] = t1;
                bf[2 * p + 1][0] = t2;
                bf[2 * p + 1][1] = t3;
            }
            uint32_t aq[4];
            ldmx4(aq[0], aq[1], aq[2], aq[3],
                  qlo_b + ((qboff + ks * 32) ^ qmsk));
#pragma unroll
            for (int nt = 0; nt < 8; nt++)
                mma_bf16(s[nt], qf[ks], bf[nt]);
#pragma unroll
            for (int nt = 0; nt < 8; nt++)
                mma_bf16(s[nt], aq, bf[nt]);
        }
#pragma unroll
        for (int ks = 0; ks < 4; ks++) {
            uint32_t bf[8][2];
#pragma unroll
            for (int p = 0; p < 4; p++) {
                uint32_t t0, t1, t2, t3;
                ldmx4(t0, t1, t2, t3,
                      kstage + 8192 + ((k_off[p] + ks * 32) ^ k_msk[p]));
                bf[2 * p][0] = t0;
                bf[2 * p][1] = t1;
                bf[2 * p + 1][0] = t2;
                bf[2 * p + 1][1] = t3;
            }
#pragma unroll
            for (int nt = 0; nt < 8; nt++)
                mma_bf16(s[nt], qf[ks], bf[nt]);
        }

        float mx0 = -1e30f, mx1 = -1e30f;
#pragma unroll
        for (int nt = 0; nt < 8; nt++) {
            mx0 = fmaxf(mx0, fmaxf(s[nt][0], s[nt][1]));
            mx1 = fmaxf(mx1, fmaxf(s[nt][2], s[nt][3]));
        }
        mx0 = fmaxf(mx0, __shfl_xor_sync(0xffffffffu, mx0, 1));
        mx0 = fmaxf(mx0, __shfl_xor_sync(0xffffffffu, mx0, 2));
        mx1 = fmaxf(mx1, __shfl_xor_sync(0xffffffffu, mx1, 1));
        mx1 = fmaxf(mx1, __shfl_xor_sync(0xffffffffu, mx1, 2));
        const float mn0 = fmaxf(m_i[0], mx0);
        const float mn1 = fmaxf(m_i[1], mx1);
        const float sc0 = __expf(m_i[0] - mn0);
        const float sc1 = __expf(m_i[1] - mn1);
        m_i[0] = mn0;
        m_i[1] = mn1;
#pragma unroll
        for (int nt = 0; nt < 8; nt++) {
            o[nt][0] *= sc0;
            o[nt][1] *= sc0;
            o[nt][2] *= sc1;
            o[nt][3] *= sc1;
        }

        float rs0 = 0.f, rs1 = 0.f;
#pragma unroll
        for (int ks = 0; ks < 4; ks++) {
            uint32_t phi_[4], plo_[4];
#pragma unroll
            for (int t = 0; t < 2; t++) {
                int nt = ks * 2 + t;
                float p00 = __expf(s[nt][0] - mn0);
                float p01 = __expf(s[nt][1] - mn0);
                float p10 = __expf(s[nt][2] - mn1);
                float p11 = __expf(s[nt][3] - mn1);
                rs0 += p00 + p01;
                rs1 += p10 + p11;
                split2(p00, p01, phi_[t * 2], plo_[t * 2]);
                split2(p10, p11, phi_[t * 2 + 1], plo_[t * 2 + 1]);
            }
            uint32_t bf[8][2];
#pragma unroll
            for (int j = 0; j < 4; j++) {
                uint32_t t0, t1, t2, t3;
                ldmx4t(t0, t1, t2, t3,
                       vstage + ((v_off[j] + ks * 2048) ^ v_msk));
                bf[2 * j][0] = t0;
                bf[2 * j][1] = t1;
                bf[2 * j + 1][0] = t2;
                bf[2 * j + 1][1] = t3;
            }
#pragma unroll
            for (int nt = 0; nt < 8; nt++)
                mma_bf16(o[nt], phi_, bf[nt]);
#pragma unroll
            for (int nt = 0; nt < 8; nt++)
                mma_bf16(o[nt], plo_, bf[nt]);
#pragma unroll
            for (int j = 0; j < 4; j++) {
                uint32_t t0, t1, t2, t3;
                ldmx4t(t0, t1, t2, t3,
                       vstage + 8192 + ((v_off[j] + ks * 2048) ^ v_msk));
                bf[2 * j][0] = t0;
                bf[2 * j][1] = t1;
                bf[2 * j + 1][0] = t2;
                bf[2 * j + 1][1] = t3;
            }
#pragma unroll
            for (int nt = 0; nt < 8; nt++)
                mma_bf16(o[nt], phi_, bf[nt]);
        }
        rs0 += __shfl_xor_sync(0xffffffffu, rs0, 1);
        rs0 += __shfl_xor_sync(0xffffffffu, rs0, 2);
        rs1 += __shfl_xor_sync(0xffffffffu, rs1, 1);
        rs1 += __shfl_xor_sync(0xffffffffu, rs1, 2);
        l_i[0] = l_i[0] * sc0 + rs0;
        l_i[1] = l_i[1] * sc1 + rs1;
    }

    const float inv0 = 1.0f / l_i[0];
    const float inv1 = 1.0f / l_i[1];
#pragma unroll
    for (int nt = 0; nt < 8; nt++) {
        int col = h * DKH + scol + nt * 8;
        size_t i0 = (size_t)(b * SEQ + q0 + r0) * DMODEL + col;
        size_t i1 = (size_t)(b * SEQ + q0 + r1) * DMODEL + col;
        uint32_t hi, lo;
        split2(o[nt][0] * inv0, o[nt][1] * inv0, hi, lo);
        *(uint32_t*)&g_Chi[i0] = hi;
        *(uint32_t*)&g_Clo[i0] = lo;
        split2(o[nt][2] * inv1, o[nt][3] * inv1, hi, lo);
        *(uint32_t*)&g_Chi[i1] = hi;
        *(uint32_t*)&g_Clo[i1] = lo;
    }
}

// -------------------------- launch ----------------------------------------
extern "C" void kernel_launch(void* const* d_in, const int* in_sizes, int n_in,
                              void* d_out, int out_size) {
    const float* hidden = (const float*)d_in[0];
    const float* pk     = (const float*)d_in[1];
    const float* pv     = (const float*)d_in[2];
    const float* bias   = (const float*)d_in[3];
    const float* Wq     = (const float*)d_in[4];
    const float* Wk     = (const float*)d_in[5];
    const float* Wv     = (const float*)d_in[6];
    const float* Wo     = (const float*)d_in[7];
    float* out = (float*)d_out;

    static int attr_done = 0;
    if (!attr_done) {
        cudaFuncSetAttribute(mma_gemm_kernel,
                             cudaFuncAttributeMaxDynamicSharedMemorySize, 98304);
        cudaFuncSetAttribute(attn_mma_kernel,
                             cudaFuncAttributeMaxDynamicSharedMemorySize, 98304);
        attr_done = 1;
    }

    prep_all_kernel<<<6656, 256>>>(hidden, pk, pv, Wq, Wk, Wv, Wo);
    mma_gemm_kernel<<<dim3(DMODEL / 128, MROWS / 128, 3), 256, 98304>>>(0, nullptr);
    attn_mma_kernel<<<dim3(BATCH * NH, SEQ / 128), 256, 98304>>>(bias);
    mma_gemm_kernel<<<dim3(DMODEL / 128, MROWS / 128, 1), 256, 98304>>>(1, out);
}